// round 10
// baseline (speedup 1.0000x reference)
#include <cuda_runtime.h>

#define KCLS 19
#define NIMG 4
#define CDIM 128
#define PPIX 131072   // 256*512

// Scratch (device globals; no allocation allowed)
__device__ unsigned char g_lab[NIMG * PPIX];
__device__ float g_sums[NIMG * KCLS * CDIM];
__device__ int   g_cnt[NIMG * 20];
__device__ float g_rsum[NIMG * KCLS];
__device__ int   g_is64;                      // 1 if target buffer is int64

// ---------------------------------------------------------------------------
// Zero accumulators + detect target dtype.
// int64 labels < 19 => every odd int32 word is 0 (little-endian).
// Reads only the first 2 KiB (in-bounds for both int32 and int64 layouts).
// ---------------------------------------------------------------------------
__global__ void k_zero_detect(const int* __restrict__ t32) {
    int tid = threadIdx.x;
    for (int i = tid; i < NIMG * KCLS * CDIM; i += 256) g_sums[i] = 0.f;
    if (tid < NIMG * 20)   g_cnt[tid] = 0;
    if (tid < NIMG * KCLS) g_rsum[tid] = 0.f;

    __shared__ int bad;
    if (tid == 0) bad = 0;
    __syncthreads();
    if (t32[tid * 2 + 1] != 0) atomicOr(&bad, 1);
    __syncthreads();
    if (tid == 0) g_is64 = bad ? 0 : 1;
}

// ---------------------------------------------------------------------------
// Convert labels (int64 OR int32, per g_is64) -> u8, histogram counts.
// grid (32, NIMG), 256 threads; each block handles 4096 pixels.
// ---------------------------------------------------------------------------
__global__ void k_prep(const void* __restrict__ tgt) {
    int n = blockIdx.y;
    int tid = threadIdx.x;
    __shared__ int h[20];
    if (tid < 20) h[tid] = 0;
    __syncthreads();

    unsigned char* lp = g_lab + (size_t)n * PPIX;
    const int is64 = g_is64;

    #pragma unroll
    for (int it = 0; it < 4; ++it) {
        int p = blockIdx.x * 4096 + it * 1024 + tid * 4;
        int v0, v1, v2, v3;
        if (is64) {
            const long long* tp = (const long long*)tgt + (size_t)n * PPIX;
            longlong2 a = *(const longlong2*)(tp + p);
            longlong2 b = *(const longlong2*)(tp + p + 2);
            v0 = (int)a.x; v1 = (int)a.y; v2 = (int)b.x; v3 = (int)b.y;
        } else {
            const int* tp = (const int*)tgt + (size_t)n * PPIX;
            int4 a = *(const int4*)(tp + p);
            v0 = a.x; v1 = a.y; v2 = a.z; v3 = a.w;
        }
        uchar4 u;
        u.x = (v0 >= 0 && v0 < KCLS) ? (unsigned char)v0 : (unsigned char)255;
        u.y = (v1 >= 0 && v1 < KCLS) ? (unsigned char)v1 : (unsigned char)255;
        u.z = (v2 >= 0 && v2 < KCLS) ? (unsigned char)v2 : (unsigned char)255;
        u.w = (v3 >= 0 && v3 < KCLS) ? (unsigned char)v3 : (unsigned char)255;
        *(uchar4*)(lp + p) = u;
        atomicAdd(&h[u.x < KCLS ? (int)u.x : 19], 1);
        atomicAdd(&h[u.y < KCLS ? (int)u.y : 19], 1);
        atomicAdd(&h[u.z < KCLS ? (int)u.z : 19], 1);
        atomicAdd(&h[u.w < KCLS ? (int)u.w : 19], 1);
    }
    __syncthreads();
    if (tid < 20) atomicAdd(&g_cnt[n * 20 + tid], h[tid]);
}

// ---------------------------------------------------------------------------
// Pass 1: segment sums.  grid (8, CDIM, NIMG), 256 threads.
// Block owns one channel, 16384-pixel chunk. Privatized smem acc [20][256].
// ---------------------------------------------------------------------------
__global__ void k_segsum(const float* __restrict__ x) {
    const int CH = 16384;
    int n = blockIdx.z, c = blockIdx.y, chunk = blockIdx.x;
    int tid = threadIdx.x;

    __shared__ float acc[20 * 256];
    #pragma unroll
    for (int k = 0; k < 20; ++k) acc[k * 256 + tid] = 0.f;
    __syncthreads();

    const float4* xp = (const float4*)(x + ((size_t)(n * CDIM + c)) * PPIX + (size_t)chunk * CH);
    const uchar4* lp = (const uchar4*)(g_lab + (size_t)n * PPIX + (size_t)chunk * CH);

    #pragma unroll 4
    for (int i = tid; i < CH / 4; i += 256) {
        float4 v = xp[i];
        uchar4 l = lp[i];
        int k0 = l.x < KCLS ? (int)l.x : 19;
        int k1 = l.y < KCLS ? (int)l.y : 19;
        int k2 = l.z < KCLS ? (int)l.z : 19;
        int k3 = l.w < KCLS ? (int)l.w : 19;
        acc[k0 * 256 + tid] += v.x;
        acc[k1 * 256 + tid] += v.y;
        acc[k2 * 256 + tid] += v.z;
        acc[k3 * 256 + tid] += v.w;
    }
    __syncthreads();

    int warp = tid >> 5, lane = tid & 31;
    for (int k = warp; k < KCLS; k += 8) {
        float s = 0.f;
        #pragma unroll
        for (int j = 0; j < 8; ++j) s += acc[k * 256 + j * 32 + lane];
        #pragma unroll
        for (int o = 16; o > 0; o >>= 1) s += __shfl_down_sync(0xffffffffu, s, o);
        if (lane == 0) atomicAdd(&g_sums[(n * KCLS + k) * CDIM + c], s);
    }
}

// ---------------------------------------------------------------------------
// Pass 2: per-pixel distance to class mean, relu margin, per-class sums.
// grid (128, NIMG), 256 threads; block covers 1024 pixels (4/thread, float4).
// Means built in-block from g_sums (transposed [c][k] in smem).
// ---------------------------------------------------------------------------
__global__ void k_var(const float* __restrict__ x) {
    int n = blockIdx.y;
    int tid = threadIdx.x;
    __shared__ float inv[20];
    __shared__ float ms[CDIM * KCLS];   // [c][k], 2432 floats
    __shared__ float rpart[KCLS];

    if (tid < 20) inv[tid] = 1.0f / fmaxf((float)g_cnt[n * 20 + tid], 1.f);
    if (tid < KCLS) rpart[tid] = 0.f;
    __syncthreads();

    for (int i = tid; i < CDIM * KCLS; i += 256) {
        int c = i / KCLS, k = i % KCLS;
        ms[i] = g_sums[(n * KCLS + k) * CDIM + c] * inv[k];
    }
    __syncthreads();

    int p0 = blockIdx.x * 1024 + tid * 4;
    uchar4 l = *(const uchar4*)(g_lab + (size_t)n * PPIX + p0);
    int b0 = l.x < KCLS ? (int)l.x : 0;
    int b1 = l.y < KCLS ? (int)l.y : 0;
    int b2 = l.z < KCLS ? (int)l.z : 0;
    int b3 = l.w < KCLS ? (int)l.w : 0;

    const float* xp = x + ((size_t)n * CDIM) * PPIX + p0;
    float a0 = 0.f, a1 = 0.f, a2 = 0.f, a3 = 0.f;

    #pragma unroll 4
    for (int c = 0; c < CDIM; ++c) {
        float4 v = *(const float4*)(xp + (size_t)c * PPIX);
        const float* mc = ms + c * KCLS;
        float t0 = mc[b0] - v.x;
        float t1 = mc[b1] - v.y;
        float t2 = mc[b2] - v.z;
        float t3 = mc[b3] - v.w;
        a0 = fmaf(t0, t0, a0);
        a1 = fmaf(t1, t1, a1);
        a2 = fmaf(t2, t2, a2);
        a3 = fmaf(t3, t3, a3);
    }

    float r0 = fmaxf(sqrtf(a0) - 0.5f, 0.f); r0 *= r0;
    float r1 = fmaxf(sqrtf(a1) - 0.5f, 0.f); r1 *= r1;
    float r2 = fmaxf(sqrtf(a2) - 0.5f, 0.f); r2 *= r2;
    float r3 = fmaxf(sqrtf(a3) - 0.5f, 0.f); r3 *= r3;
    if (l.x < KCLS) atomicAdd(&rpart[l.x], r0);
    if (l.y < KCLS) atomicAdd(&rpart[l.y], r1);
    if (l.z < KCLS) atomicAdd(&rpart[l.z], r2);
    if (l.w < KCLS) atomicAdd(&rpart[l.w], r3);
    __syncthreads();
    if (tid < KCLS) atomicAdd(&g_rsum[n * KCLS + tid], rpart[tid]);
}

// ---------------------------------------------------------------------------
// Final scalar: loss_var + loss_dis + 0.001 * loss_reg, mean over images.
// 1 block, 512 threads. Means in smem padded to stride 129 (bank-safe).
// ---------------------------------------------------------------------------
__global__ void k_final(float* __restrict__ out) {
    __shared__ float m[KCLS * 129];
    __shared__ float s_var, s_dis, s_reg;
    int tid = threadIdx.x;
    float total = 0.f;   // meaningful on tid 0 only

    for (int n = 0; n < NIMG; ++n) {
        if (tid == 0) { s_var = 0.f; s_dis = 0.f; s_reg = 0.f; }
        __syncthreads();

        for (int i = tid; i < KCLS * CDIM; i += 512) {
            int k = i / CDIM, c = i % CDIM;
            float cnt = fmaxf((float)g_cnt[n * 20 + k], 1.f);
            m[k * 129 + c] = g_sums[(n * KCLS + k) * CDIM + c] / cnt;
        }
        __syncthreads();

        if (tid < KCLS) {
            int cnt = g_cnt[n * 20 + tid];
            if (cnt > 20) {
                atomicAdd(&s_var, g_rsum[n * KCLS + tid] / (float)cnt);
                float nr = 0.f;
                #pragma unroll 4
                for (int c = 0; c < CDIM; ++c) {
                    float mv = m[tid * 129 + c];
                    nr = fmaf(mv, mv, nr);
                }
                atomicAdd(&s_reg, sqrtf(nr));
            }
        }
        if (tid < KCLS * KCLS) {
            int f = tid / KCLS, s = tid % KCLS;
            if (f != s && g_cnt[n * 20 + f] > 20 && g_cnt[n * 20 + s] > 20) {
                float d2 = 0.f;
                #pragma unroll 4
                for (int c = 0; c < CDIM; ++c) {
                    float d = m[f * 129 + c] - m[s * 129 + c];
                    d2 = fmaf(d, d, d2);
                }
                float t = fmaxf(3.0f - sqrtf(d2), 0.f);   // 2*DELTA = 3.0
                atomicAdd(&s_dis, t * t);
            }
        }
        __syncthreads();

        if (tid == 0) {
            int nvi = 0;
            for (int k = 0; k < KCLS; ++k) nvi += (g_cnt[n * 20 + k] > 20);
            float nv = fmaxf((float)nvi, 1.f);
            float connect = fmaxf(nv * (nv - 1.f), 1.f);
            total += s_var / nv + s_dis / connect + 0.001f * s_reg / nv;
        }
        __syncthreads();
    }
    if (tid == 0) out[0] = total * 0.25f;
}

// ---------------------------------------------------------------------------
extern "C" void kernel_launch(void* const* d_in, const int* in_sizes, int n_in,
                              void* d_out, int out_size) {
    int pi = 0, ti = 1;
    if (n_in >= 2 && in_sizes[0] == NIMG * PPIX) { pi = 1; ti = 0; }  // robustness vs input order
    const float* predict = (const float*)d_in[pi];
    const void* target = (const void*)d_in[ti];
    float* out = (float*)d_out;

    k_zero_detect<<<1, 256>>>((const int*)target);
    k_prep<<<dim3(PPIX / 4096, NIMG), 256>>>(target);
    k_segsum<<<dim3(PPIX / 16384, CDIM, NIMG), 256>>>(predict);
    k_var<<<dim3(PPIX / 1024, NIMG), 256>>>(predict);
    k_final<<<1, 512>>>(out);
}

// round 12
// speedup vs baseline: 1.1172x; 1.1172x over previous
#include <cuda_runtime.h>

#define KCLS 19
#define NIMG 4
#define CDIM 128
#define PPIX 131072   // 256*512
#define NB   296      // persistent grid: 2 blocks/SM on 148 SMs (all co-resident)
#define NT   256

// Scratch (device globals; no allocation allowed)
__device__ unsigned char g_lab[NIMG * PPIX];
__device__ float g_sums[NIMG * KCLS * CDIM];
__device__ int   g_hist[128 * 20];          // per-prep-item partial histograms
__device__ float g_rsum[NIMG * KCLS];
__device__ int   g_barcnt;                  // zero-init, returns to 0 after each barrier
__device__ int   g_bargen;                  // monotone generation counter

// Global barrier: sense-reversal via generation counter. Requires all NB
// blocks co-resident (enforced by __launch_bounds__(NT,2), grid=2*148).
__device__ __forceinline__ void gbar() {
    __syncthreads();
    if (threadIdx.x == 0) {
        __threadfence();
        int gen = *(volatile int*)&g_bargen;
        if (atomicAdd(&g_barcnt, 1) == NB - 1) {
            atomicExch(&g_barcnt, 0);
            __threadfence();
            atomicAdd(&g_bargen, 1);
        } else {
            while (*(volatile int*)&g_bargen == gen) __nanosleep(128);
        }
        __threadfence();
    }
    __syncthreads();
}

__global__ void __launch_bounds__(NT, 2)
k_all(const float* __restrict__ x, const void* __restrict__ tgt,
      const int* __restrict__ t32, float* __restrict__ out) {
    __shared__ __align__(16) char smraw[39936];
    const int tid = threadIdx.x;
    const int bid = blockIdx.x;

    // dtype detect, redundantly per block (int64 labels<19 => odd words all 0)
    int w = t32[tid * 2 + 1];
    int is64 = __syncthreads_and(w == 0);

    // ================= phase 0: labels + histograms + zeroing =================
    if (bid < 128) {
        int* h = (int*)smraw;
        if (tid < 20) h[tid] = 0;
        __syncthreads();
        int n = bid >> 5, blk = bid & 31;
        unsigned char* lp = g_lab + (size_t)n * PPIX;
        #pragma unroll
        for (int it = 0; it < 4; ++it) {
            int p = blk * 4096 + it * 1024 + tid * 4;
            int v0, v1, v2, v3;
            if (is64) {
                const long long* tp = (const long long*)tgt + (size_t)n * PPIX;
                longlong2 a = *(const longlong2*)(tp + p);
                longlong2 b = *(const longlong2*)(tp + p + 2);
                v0 = (int)a.x; v1 = (int)a.y; v2 = (int)b.x; v3 = (int)b.y;
            } else {
                const int* tp = (const int*)tgt + (size_t)n * PPIX;
                int4 a = *(const int4*)(tp + p);
                v0 = a.x; v1 = a.y; v2 = a.z; v3 = a.w;
            }
            uchar4 u;
            u.x = (v0 >= 0 && v0 < KCLS) ? (unsigned char)v0 : (unsigned char)255;
            u.y = (v1 >= 0 && v1 < KCLS) ? (unsigned char)v1 : (unsigned char)255;
            u.z = (v2 >= 0 && v2 < KCLS) ? (unsigned char)v2 : (unsigned char)255;
            u.w = (v3 >= 0 && v3 < KCLS) ? (unsigned char)v3 : (unsigned char)255;
            *(uchar4*)(lp + p) = u;
            atomicAdd(&h[u.x < KCLS ? (int)u.x : 19], 1);
            atomicAdd(&h[u.y < KCLS ? (int)u.y : 19], 1);
            atomicAdd(&h[u.z < KCLS ? (int)u.z : 19], 1);
            atomicAdd(&h[u.w < KCLS ? (int)u.w : 19], 1);
        }
        __syncthreads();
        if (tid < 20) g_hist[bid * 20 + tid] = h[tid];
    } else if (bid < 166) {
        int idx = (bid - 128) * 256 + tid;
        if (idx < NIMG * KCLS * CDIM) g_sums[idx] = 0.f;
    } else if (bid == 166) {
        if (tid < NIMG * KCLS) g_rsum[tid] = 0.f;
    }
    gbar();

    // ================= phase 1: segment sums =================
    {
        float* acc = (float*)smraw;   // [20][256]
        for (int item = bid; item < 4096; item += NB) {
            int n = item >> 10, rem = item & 1023, c = rem >> 3, chunk = rem & 7;
            #pragma unroll
            for (int k = 0; k < 20; ++k) acc[k * 256 + tid] = 0.f;
            __syncthreads();

            const float4* xp = (const float4*)(x + ((size_t)(n * CDIM + c)) * PPIX + (size_t)chunk * 16384);
            const uchar4* lp = (const uchar4*)(g_lab + (size_t)n * PPIX + (size_t)chunk * 16384);
            #pragma unroll 4
            for (int i = tid; i < 4096; i += 256) {
                float4 v = xp[i];
                uchar4 l = lp[i];
                int k0 = l.x < KCLS ? (int)l.x : 19;
                int k1 = l.y < KCLS ? (int)l.y : 19;
                int k2 = l.z < KCLS ? (int)l.z : 19;
                int k3 = l.w < KCLS ? (int)l.w : 19;
                acc[k0 * 256 + tid] += v.x;
                acc[k1 * 256 + tid] += v.y;
                acc[k2 * 256 + tid] += v.z;
                acc[k3 * 256 + tid] += v.w;
            }
            __syncthreads();

            int warp = tid >> 5, lane = tid & 31;
            for (int k = warp; k < KCLS; k += 8) {
                float s = 0.f;
                #pragma unroll
                for (int j = 0; j < 8; ++j) s += acc[k * 256 + j * 32 + lane];
                #pragma unroll
                for (int o = 16; o > 0; o >>= 1) s += __shfl_down_sync(0xffffffffu, s, o);
                if (lane == 0) atomicAdd(&g_sums[(n * KCLS + k) * CDIM + c], s);
            }
            __syncthreads();
        }
    }
    gbar();

    // ================= phase 2: per-pixel variance term =================
    float* ms    = (float*)smraw;             // [4][128][19] = 9728 floats
    float* inv   = (float*)(smraw + 38912);   // [4][20]
    int*   scnt  = (int*)  (smraw + 39232);   // [4][20]
    float* rpart = (float*)(smraw + 39552);   // [19]
    float* ssc   = (float*)(smraw + 39628);   // 3 scalars (phase 3)

    if (tid < 80) {
        int n = tid / 20, k = tid % 20, sum = 0;
        #pragma unroll 4
        for (int b = 0; b < 32; ++b) sum += g_hist[(n * 32 + b) * 20 + k];
        scnt[tid] = sum;
        inv[tid] = 1.0f / fmaxf((float)sum, 1.f);
    }
    __syncthreads();
    for (int i = tid; i < NIMG * CDIM * KCLS; i += 256) {
        int n = i / (CDIM * KCLS), r = i % (CDIM * KCLS), c = r / KCLS, k = r % KCLS;
        ms[i] = g_sums[(n * KCLS + k) * CDIM + c] * inv[n * 20 + k];
    }
    __syncthreads();

    for (int item = bid; item < 512; item += NB) {
        int n = item >> 7, tile = item & 127;
        if (tid < KCLS) rpart[tid] = 0.f;
        __syncthreads();

        int p0 = tile * 1024 + tid * 4;
        uchar4 l = *(const uchar4*)(g_lab + (size_t)n * PPIX + p0);
        int b0 = l.x < KCLS ? (int)l.x : 0;
        int b1 = l.y < KCLS ? (int)l.y : 0;
        int b2 = l.z < KCLS ? (int)l.z : 0;
        int b3 = l.w < KCLS ? (int)l.w : 0;

        const float* xp = x + ((size_t)n * CDIM) * PPIX + p0;
        float a0 = 0.f, a1 = 0.f, a2 = 0.f, a3 = 0.f;
        #pragma unroll 4
        for (int c = 0; c < CDIM; ++c) {
            float4 v = *(const float4*)(xp + (size_t)c * PPIX);
            const float* mc = ms + (n * CDIM + c) * KCLS;
            float t0 = mc[b0] - v.x;
            float t1 = mc[b1] - v.y;
            float t2 = mc[b2] - v.z;
            float t3 = mc[b3] - v.w;
            a0 = fmaf(t0, t0, a0);
            a1 = fmaf(t1, t1, a1);
            a2 = fmaf(t2, t2, a2);
            a3 = fmaf(t3, t3, a3);
        }
        float r0 = fmaxf(sqrtf(a0) - 0.5f, 0.f); r0 *= r0;
        float r1 = fmaxf(sqrtf(a1) - 0.5f, 0.f); r1 *= r1;
        float r2 = fmaxf(sqrtf(a2) - 0.5f, 0.f); r2 *= r2;
        float r3 = fmaxf(sqrtf(a3) - 0.5f, 0.f); r3 *= r3;
        if (l.x < KCLS) atomicAdd(&rpart[l.x], r0);
        if (l.y < KCLS) atomicAdd(&rpart[l.y], r1);
        if (l.z < KCLS) atomicAdd(&rpart[l.z], r2);
        if (l.w < KCLS) atomicAdd(&rpart[l.w], r3);
        __syncthreads();
        if (tid < KCLS) atomicAdd(&g_rsum[n * KCLS + tid], rpart[tid]);
        __syncthreads();
    }
    gbar();

    // ================= phase 3: final scalar (block 0 only) =================
    if (bid == 0) {
        float total = 0.f;   // meaningful on tid 0 only
        for (int n = 0; n < NIMG; ++n) {
            if (tid == 0) { ssc[0] = 0.f; ssc[1] = 0.f; ssc[2] = 0.f; }
            __syncthreads();

            if (tid < KCLS) {
                int cnt = scnt[n * 20 + tid];
                if (cnt > 20) {
                    atomicAdd(&ssc[0], g_rsum[n * KCLS + tid] / (float)cnt);
                    float nr = 0.f;
                    #pragma unroll 4
                    for (int c = 0; c < CDIM; ++c) {
                        float mv = ms[(n * CDIM + c) * KCLS + tid];
                        nr = fmaf(mv, mv, nr);
                    }
                    atomicAdd(&ssc[2], sqrtf(nr));
                }
            }
            for (int idx = tid; idx < KCLS * KCLS; idx += 256) {
                int f = idx / KCLS, s = idx % KCLS;
                if (f != s && scnt[n * 20 + f] > 20 && scnt[n * 20 + s] > 20) {
                    float d2 = 0.f;
                    #pragma unroll 4
                    for (int c = 0; c < CDIM; ++c) {
                        float d = ms[(n * CDIM + c) * KCLS + f] - ms[(n * CDIM + c) * KCLS + s];
                        d2 = fmaf(d, d, d2);
                    }
                    float t = fmaxf(3.0f - sqrtf(d2), 0.f);   // 2*DELTA = 3.0
                    atomicAdd(&ssc[1], t * t);
                }
            }
            __syncthreads();

            if (tid == 0) {
                int nvi = 0;
                for (int k = 0; k < KCLS; ++k) nvi += (scnt[n * 20 + k] > 20);
                float nv = fmaxf((float)nvi, 1.f);
                float connect = fmaxf(nv * (nv - 1.f), 1.f);
                total += ssc[0] / nv + ssc[1] / connect + 0.001f * ssc[2] / nv;
            }
            __syncthreads();
        }
        if (tid == 0) out[0] = total * 0.25f;
    }
}

// ---------------------------------------------------------------------------
extern "C" void kernel_launch(void* const* d_in, const int* in_sizes, int n_in,
                              void* d_out, int out_size) {
    int pi = 0, ti = 1;
    if (n_in >= 2 && in_sizes[0] == NIMG * PPIX) { pi = 1; ti = 0; }  // robustness vs input order
    const float* predict = (const float*)d_in[pi];
    const void* target = (const void*)d_in[ti];
    float* out = (float*)d_out;

    k_all<<<NB, NT>>>(predict, target, (const int*)target, out);
}

// round 13
// speedup vs baseline: 1.3758x; 1.2315x over previous
#include <cuda_runtime.h>

#define KCLS 19
#define NIMG 4
#define CDIM 128
#define PPIX 131072   // 256*512
#define NB   592      // persistent grid: 4 blocks/SM on 148 SMs (all co-resident)
#define NT   256

// Scratch (device globals; no allocation allowed)
__device__ unsigned char g_lab[NIMG * PPIX];
__device__ float g_sums[NIMG * KCLS * CDIM];
__device__ int   g_hist[128 * 20];          // per-prep-item partial histograms
__device__ float g_rsum[NIMG * KCLS];
__device__ int   g_barcnt;                  // zero-init, returns to 0 after each barrier
__device__ int   g_bargen;                  // monotone generation counter

// Global barrier: sense-reversal via generation counter. Requires all NB
// blocks co-resident (enforced by __launch_bounds__(NT,4), grid=4*148).
__device__ __forceinline__ void gbar() {
    __syncthreads();
    if (threadIdx.x == 0) {
        __threadfence();
        int gen = *(volatile int*)&g_bargen;
        if (atomicAdd(&g_barcnt, 1) == NB - 1) {
            atomicExch(&g_barcnt, 0);
            __threadfence();
            atomicAdd(&g_bargen, 1);
        } else {
            while (*(volatile int*)&g_bargen == gen) __nanosleep(64);
        }
        __threadfence();
    }
    __syncthreads();
}

// Shared-memory union: phase1 acc[20*256]=20480B; phase2/3 tables ~10.5KB.
#define SM_BYTES 20480
#define OFF_MS    0        // float ms[2432]   (one image: [c][k])
#define OFF_INV   9728     // float inv[80]
#define OFF_SCNT  10048    // int   scnt[80]
#define OFF_RPART 10368    // float rpart[19]
#define OFF_SSC   10448    // float ssc[3]

__global__ void __launch_bounds__(NT, 4)
k_all(const float* __restrict__ x, const void* __restrict__ tgt,
      const int* __restrict__ t32, float* __restrict__ out) {
    __shared__ __align__(16) char smraw[SM_BYTES];
    const int tid = threadIdx.x;
    const int bid = blockIdx.x;

    // dtype detect, redundantly per block (int64 labels<19 => odd words all 0)
    int w = t32[tid * 2 + 1];
    int is64 = __syncthreads_and(w == 0);

    // ================= phase 0: labels + histograms + zeroing =================
    if (bid < 128) {
        int* h = (int*)smraw;
        if (tid < 20) h[tid] = 0;
        __syncthreads();
        int n = bid >> 5, blk = bid & 31;
        unsigned char* lp = g_lab + (size_t)n * PPIX;
        #pragma unroll
        for (int it = 0; it < 4; ++it) {
            int p = blk * 4096 + it * 1024 + tid * 4;
            int v0, v1, v2, v3;
            if (is64) {
                const long long* tp = (const long long*)tgt + (size_t)n * PPIX;
                longlong2 a = *(const longlong2*)(tp + p);
                longlong2 b = *(const longlong2*)(tp + p + 2);
                v0 = (int)a.x; v1 = (int)a.y; v2 = (int)b.x; v3 = (int)b.y;
            } else {
                const int* tp = (const int*)tgt + (size_t)n * PPIX;
                int4 a = *(const int4*)(tp + p);
                v0 = a.x; v1 = a.y; v2 = a.z; v3 = a.w;
            }
            uchar4 u;
            u.x = (v0 >= 0 && v0 < KCLS) ? (unsigned char)v0 : (unsigned char)255;
            u.y = (v1 >= 0 && v1 < KCLS) ? (unsigned char)v1 : (unsigned char)255;
            u.z = (v2 >= 0 && v2 < KCLS) ? (unsigned char)v2 : (unsigned char)255;
            u.w = (v3 >= 0 && v3 < KCLS) ? (unsigned char)v3 : (unsigned char)255;
            *(uchar4*)(lp + p) = u;
            atomicAdd(&h[u.x < KCLS ? (int)u.x : 19], 1);
            atomicAdd(&h[u.y < KCLS ? (int)u.y : 19], 1);
            atomicAdd(&h[u.z < KCLS ? (int)u.z : 19], 1);
            atomicAdd(&h[u.w < KCLS ? (int)u.w : 19], 1);
        }
        __syncthreads();
        if (tid < 20) g_hist[bid * 20 + tid] = h[tid];
    } else if (bid < 166) {
        int idx = (bid - 128) * 256 + tid;
        if (idx < NIMG * KCLS * CDIM) g_sums[idx] = 0.f;
    } else if (bid == 166) {
        if (tid < NIMG * KCLS) g_rsum[tid] = 0.f;
    }
    gbar();

    // ================= phase 1: segment sums =================
    {
        float* acc = (float*)smraw;   // [20][256]
        for (int item = bid; item < 4096; item += NB) {
            int n = item >> 10, rem = item & 1023, c = rem >> 3, chunk = rem & 7;
            #pragma unroll
            for (int k = 0; k < 20; ++k) acc[k * 256 + tid] = 0.f;
            __syncthreads();

            const float4* xp = (const float4*)(x + ((size_t)(n * CDIM + c)) * PPIX + (size_t)chunk * 16384);
            const uchar4* lp = (const uchar4*)(g_lab + (size_t)n * PPIX + (size_t)chunk * 16384);
            #pragma unroll 4
            for (int i = tid; i < 4096; i += 256) {
                float4 v = xp[i];
                uchar4 l = lp[i];
                int k0 = l.x < KCLS ? (int)l.x : 19;
                int k1 = l.y < KCLS ? (int)l.y : 19;
                int k2 = l.z < KCLS ? (int)l.z : 19;
                int k3 = l.w < KCLS ? (int)l.w : 19;
                acc[k0 * 256 + tid] += v.x;
                acc[k1 * 256 + tid] += v.y;
                acc[k2 * 256 + tid] += v.z;
                acc[k3 * 256 + tid] += v.w;
            }
            __syncthreads();

            int warp = tid >> 5, lane = tid & 31;
            for (int k = warp; k < KCLS; k += 8) {
                float s = 0.f;
                #pragma unroll
                for (int j = 0; j < 8; ++j) s += acc[k * 256 + j * 32 + lane];
                #pragma unroll
                for (int o = 16; o > 0; o >>= 1) s += __shfl_down_sync(0xffffffffu, s, o);
                if (lane == 0) atomicAdd(&g_sums[(n * KCLS + k) * CDIM + c], s);
            }
            __syncthreads();
        }
    }
    gbar();

    // ================= phase 2: per-pixel variance term =================
    float* ms    = (float*)(smraw + OFF_MS);     // one image, [c][k]
    float* inv   = (float*)(smraw + OFF_INV);
    int*   scnt  = (int*)  (smraw + OFF_SCNT);
    float* rpart = (float*)(smraw + OFF_RPART);
    float* ssc   = (float*)(smraw + OFF_SSC);

    if (tid < 80) {
        int n = tid / 20, k = tid % 20, sum = 0;
        #pragma unroll 4
        for (int b = 0; b < 32; ++b) sum += g_hist[(n * 32 + b) * 20 + k];
        scnt[tid] = sum;
        inv[tid] = 1.0f / fmaxf((float)sum, 1.f);
    }
    __syncthreads();

    if (bid < 512) {
        int n = bid >> 7, tile = bid & 127;

        // build means table for THIS image only (2432 floats, L2-fed)
        for (int i = tid; i < CDIM * KCLS; i += 256) {
            int c = i / KCLS, k = i % KCLS;
            ms[i] = g_sums[(n * KCLS + k) * CDIM + c] * inv[n * 20 + k];
        }
        if (tid < KCLS) rpart[tid] = 0.f;
        __syncthreads();

        int p0 = tile * 1024 + tid * 4;
        uchar4 l = *(const uchar4*)(g_lab + (size_t)n * PPIX + p0);
        int b0 = l.x < KCLS ? (int)l.x : 0;
        int b1 = l.y < KCLS ? (int)l.y : 0;
        int b2 = l.z < KCLS ? (int)l.z : 0;
        int b3 = l.w < KCLS ? (int)l.w : 0;

        const float* xp = x + ((size_t)n * CDIM) * PPIX + p0;
        float a0 = 0.f, a1 = 0.f, a2 = 0.f, a3 = 0.f;
        #pragma unroll 4
        for (int c = 0; c < CDIM; ++c) {
            float4 v = *(const float4*)(xp + (size_t)c * PPIX);
            const float* mc = ms + c * KCLS;
            float t0 = mc[b0] - v.x;
            float t1 = mc[b1] - v.y;
            float t2 = mc[b2] - v.z;
            float t3 = mc[b3] - v.w;
            a0 = fmaf(t0, t0, a0);
            a1 = fmaf(t1, t1, a1);
            a2 = fmaf(t2, t2, a2);
            a3 = fmaf(t3, t3, a3);
        }
        float r0 = fmaxf(sqrtf(a0) - 0.5f, 0.f); r0 *= r0;
        float r1 = fmaxf(sqrtf(a1) - 0.5f, 0.f); r1 *= r1;
        float r2 = fmaxf(sqrtf(a2) - 0.5f, 0.f); r2 *= r2;
        float r3 = fmaxf(sqrtf(a3) - 0.5f, 0.f); r3 *= r3;
        if (l.x < KCLS) atomicAdd(&rpart[l.x], r0);
        if (l.y < KCLS) atomicAdd(&rpart[l.y], r1);
        if (l.z < KCLS) atomicAdd(&rpart[l.z], r2);
        if (l.w < KCLS) atomicAdd(&rpart[l.w], r3);
        __syncthreads();
        if (tid < KCLS) atomicAdd(&g_rsum[n * KCLS + tid], rpart[tid]);
    }
    gbar();

    // ================= phase 3: final scalar (block 0 only) =================
    if (bid == 0) {
        float total = 0.f;   // meaningful on tid 0 only
        for (int n = 0; n < NIMG; ++n) {
            // rebuild this image's means table
            for (int i = tid; i < CDIM * KCLS; i += 256) {
                int c = i / KCLS, k = i % KCLS;
                ms[i] = g_sums[(n * KCLS + k) * CDIM + c] * inv[n * 20 + k];
            }
            if (tid == 0) { ssc[0] = 0.f; ssc[1] = 0.f; ssc[2] = 0.f; }
            __syncthreads();

            if (tid < KCLS) {
                int cnt = scnt[n * 20 + tid];
                if (cnt > 20) {
                    atomicAdd(&ssc[0], g_rsum[n * KCLS + tid] / (float)cnt);
                    float nr = 0.f;
                    #pragma unroll 4
                    for (int c = 0; c < CDIM; ++c) {
                        float mv = ms[c * KCLS + tid];
                        nr = fmaf(mv, mv, nr);
                    }
                    atomicAdd(&ssc[2], sqrtf(nr));
                }
            }
            for (int idx = tid; idx < KCLS * KCLS; idx += 256) {
                int f = idx / KCLS, s = idx % KCLS;
                if (f != s && scnt[n * 20 + f] > 20 && scnt[n * 20 + s] > 20) {
                    float d2 = 0.f;
                    #pragma unroll 4
                    for (int c = 0; c < CDIM; ++c) {
                        float d = ms[c * KCLS + f] - ms[c * KCLS + s];
                        d2 = fmaf(d, d, d2);
                    }
                    float t = fmaxf(3.0f - sqrtf(d2), 0.f);   // 2*DELTA = 3.0
                    atomicAdd(&ssc[1], t * t);
                }
            }
            __syncthreads();

            if (tid == 0) {
                int nvi = 0;
                for (int k = 0; k < KCLS; ++k) nvi += (scnt[n * 20 + k] > 20);
                float nv = fmaxf((float)nvi, 1.f);
                float connect = fmaxf(nv * (nv - 1.f), 1.f);
                total += ssc[0] / nv + ssc[1] / connect + 0.001f * ssc[2] / nv;
            }
            __syncthreads();
        }
        if (tid == 0) out[0] = total * 0.25f;
    }
}

// ---------------------------------------------------------------------------
extern "C" void kernel_launch(void* const* d_in, const int* in_sizes, int n_in,
                              void* d_out, int out_size) {
    int pi = 0, ti = 1;
    if (n_in >= 2 && in_sizes[0] == NIMG * PPIX) { pi = 1; ti = 0; }  // robustness vs input order
    const float* predict = (const float*)d_in[pi];
    const void* target = (const void*)d_in[ti];
    float* out = (float*)d_out;

    k_all<<<NB, NT>>>(predict, target, (const int*)target, out);
}

// round 16
// speedup vs baseline: 1.4764x; 1.0731x over previous
#include <cuda_runtime.h>

#define KCLS 19
#define NIMG 4
#define CDIM 128
#define PPIX 131072   // 256*512
#define NB   1036     // persistent grid: 7 blocks/SM on 148 SMs (all co-resident)
#define NT   256

// Scratch (device globals; no allocation allowed)
__device__ unsigned char g_lab[NIMG * PPIX];
__device__ float g_sums[NIMG * KCLS * CDIM];
__device__ int   g_hist[256 * 20];          // per-prep-item partial histograms
__device__ float g_rsum[NIMG * KCLS];
__device__ int   g_barcnt;                  // zero-init, returns to 0 after each barrier
__device__ int   g_bargen;                  // monotone generation counter

// Global barrier: sense-reversal via generation counter. Requires all NB
// blocks co-resident (enforced by __launch_bounds__(NT,7), grid=7*148).
__device__ __forceinline__ void gbar() {
    __syncthreads();
    if (threadIdx.x == 0) {
        __threadfence();
        int gen = *(volatile int*)&g_bargen;
        if (atomicAdd(&g_barcnt, 1) == NB - 1) {
            atomicExch(&g_barcnt, 0);
            __threadfence();
            atomicAdd(&g_bargen, 1);
        } else {
            while (*(volatile int*)&g_bargen == gen) __nanosleep(64);
        }
        __threadfence();
    }
    __syncthreads();
}

// Shared-memory union: phase1 acc[20*256]=20480B; phase2/3 tables ~10.5KB.
#define SM_BYTES 20480
#define OFF_MS    0        // float ms[2432]   (one image: [c][k])
#define OFF_INV   9728     // float inv[80]
#define OFF_SCNT  10048    // int   scnt[80]
#define OFF_RPART 10368    // float rpart[19]
#define OFF_SSC   10448    // float ssc[3]

__global__ void __launch_bounds__(NT, 7)
k_all(const float* __restrict__ x, const void* __restrict__ tgt,
      const int* __restrict__ t32, float* __restrict__ out) {
    __shared__ __align__(16) char smraw[SM_BYTES];
    const int tid = threadIdx.x;
    const int bid = blockIdx.x;

    // dtype detect, redundantly per block (int64 labels<19 => odd words all 0)
    int w = t32[tid * 2 + 1];
    int is64 = __syncthreads_and(w == 0);

    // ================= phase 0: labels + histograms + zeroing =================
    if (bid < 256) {
        int* h = (int*)smraw;
        if (tid < 20) h[tid] = 0;
        __syncthreads();
        int n = bid >> 6, blk = bid & 63;
        unsigned char* lp = g_lab + (size_t)n * PPIX;
        #pragma unroll
        for (int it = 0; it < 2; ++it) {
            int p = blk * 2048 + it * 1024 + tid * 4;
            int v0, v1, v2, v3;
            if (is64) {
                const long long* tp = (const long long*)tgt + (size_t)n * PPIX;
                longlong2 a = *(const longlong2*)(tp + p);
                longlong2 b = *(const longlong2*)(tp + p + 2);
                v0 = (int)a.x; v1 = (int)a.y; v2 = (int)b.x; v3 = (int)b.y;
            } else {
                const int* tp = (const int*)tgt + (size_t)n * PPIX;
                int4 a = *(const int4*)(tp + p);
                v0 = a.x; v1 = a.y; v2 = a.z; v3 = a.w;
            }
            uchar4 u;
            u.x = (v0 >= 0 && v0 < KCLS) ? (unsigned char)v0 : (unsigned char)255;
            u.y = (v1 >= 0 && v1 < KCLS) ? (unsigned char)v1 : (unsigned char)255;
            u.z = (v2 >= 0 && v2 < KCLS) ? (unsigned char)v2 : (unsigned char)255;
            u.w = (v3 >= 0 && v3 < KCLS) ? (unsigned char)v3 : (unsigned char)255;
            *(uchar4*)(lp + p) = u;
            atomicAdd(&h[u.x < KCLS ? (int)u.x : 19], 1);
            atomicAdd(&h[u.y < KCLS ? (int)u.y : 19], 1);
            atomicAdd(&h[u.z < KCLS ? (int)u.z : 19], 1);
            atomicAdd(&h[u.w < KCLS ? (int)u.w : 19], 1);
        }
        __syncthreads();
        if (tid < 20) g_hist[bid * 20 + tid] = h[tid];
    } else if (bid < 294) {
        int idx = (bid - 256) * 256 + tid;
        if (idx < NIMG * KCLS * CDIM) g_sums[idx] = 0.f;
    } else if (bid == 294) {
        if (tid < NIMG * KCLS) g_rsum[tid] = 0.f;
    }
    gbar();

    // ================= phase 1: segment sums =================
    // 2048 items: (n, c, quarter). Each item = 32768 px of one channel.
    {
        float* acc = (float*)smraw;   // [20][256]
        for (int item = bid; item < 2048; item += NB) {
            int n = item >> 9, rem = item & 511, c = rem >> 2, q = rem & 3;
            #pragma unroll
            for (int k = 0; k < 20; ++k) acc[k * 256 + tid] = 0.f;
            __syncthreads();

            const float4* xp = (const float4*)(x + ((size_t)(n * CDIM + c)) * PPIX + (size_t)q * 32768);
            const uchar4* lp = (const uchar4*)(g_lab + (size_t)n * PPIX + (size_t)q * 32768);
            #pragma unroll 4
            for (int i = tid; i < 8192; i += 256) {
                float4 v = xp[i];
                uchar4 l = lp[i];
                int k0 = l.x < KCLS ? (int)l.x : 19;
                int k1 = l.y < KCLS ? (int)l.y : 19;
                int k2 = l.z < KCLS ? (int)l.z : 19;
                int k3 = l.w < KCLS ? (int)l.w : 19;
                acc[k0 * 256 + tid] += v.x;
                acc[k1 * 256 + tid] += v.y;
                acc[k2 * 256 + tid] += v.z;
                acc[k3 * 256 + tid] += v.w;
            }
            __syncthreads();

            int warp = tid >> 5, lane = tid & 31;
            for (int k = warp; k < KCLS; k += 8) {
                float s = 0.f;
                #pragma unroll
                for (int j = 0; j < 8; ++j) s += acc[k * 256 + j * 32 + lane];
                #pragma unroll
                for (int o = 16; o > 0; o >>= 1) s += __shfl_down_sync(0xffffffffu, s, o);
                if (lane == 0) atomicAdd(&g_sums[(n * KCLS + k) * CDIM + c], s);
            }
            __syncthreads();
        }
    }
    gbar();

    // ================= phase 2: per-pixel variance term =================
    float* ms    = (float*)(smraw + OFF_MS);     // one image, [c][k]
    float* inv   = (float*)(smraw + OFF_INV);
    int*   scnt  = (int*)  (smraw + OFF_SCNT);
    float* rpart = (float*)(smraw + OFF_RPART);
    float* ssc   = (float*)(smraw + OFF_SSC);

    if (tid < 80) {
        int n = tid / 20, k = tid % 20, sum = 0;
        #pragma unroll 4
        for (int b = 0; b < 64; ++b) sum += g_hist[(n * 64 + b) * 20 + k];
        scnt[tid] = sum;
        inv[tid] = 1.0f / fmaxf((float)sum, 1.f);
    }
    __syncthreads();

    // 1024 tiles of 512 px (one per block, all blocks start together)
    if (bid < 1024) {
        int n = bid >> 8, tile = bid & 255;

        // build means table for THIS image only (2432 floats, L2-fed)
        for (int i = tid; i < CDIM * KCLS; i += 256) {
            int c = i / KCLS, k = i % KCLS;
            ms[i] = g_sums[(n * KCLS + k) * CDIM + c] * inv[n * 20 + k];
        }
        if (tid < KCLS) rpart[tid] = 0.f;
        __syncthreads();

        int p0 = tile * 512 + tid * 2;
        uchar2 l = *(const uchar2*)(g_lab + (size_t)n * PPIX + p0);
        int b0 = l.x < KCLS ? (int)l.x : 0;
        int b1 = l.y < KCLS ? (int)l.y : 0;

        const float* xp = x + ((size_t)n * CDIM) * PPIX + p0;
        float a0 = 0.f, a1 = 0.f;
        #pragma unroll 4
        for (int c = 0; c < CDIM; ++c) {
            float2 v = *(const float2*)(xp + (size_t)c * PPIX);
            const float* mc = ms + c * KCLS;
            float t0 = mc[b0] - v.x;
            float t1 = mc[b1] - v.y;
            a0 = fmaf(t0, t0, a0);
            a1 = fmaf(t1, t1, a1);
        }
        float r0 = fmaxf(sqrtf(a0) - 0.5f, 0.f); r0 *= r0;
        float r1 = fmaxf(sqrtf(a1) - 0.5f, 0.f); r1 *= r1;
        if (l.x < KCLS) atomicAdd(&rpart[l.x], r0);
        if (l.y < KCLS) atomicAdd(&rpart[l.y], r1);
        __syncthreads();
        if (tid < KCLS) atomicAdd(&g_rsum[n * KCLS + tid], rpart[tid]);
    }
    gbar();

    // ================= phase 3: final scalar (block 0 only) =================
    if (bid == 0) {
        float total = 0.f;   // meaningful on tid 0 only
        for (int n = 0; n < NIMG; ++n) {
            // rebuild this image's means table
            for (int i = tid; i < CDIM * KCLS; i += 256) {
                int c = i / KCLS, k = i % KCLS;
                ms[i] = g_sums[(n * KCLS + k) * CDIM + c] * inv[n * 20 + k];
            }
            if (tid == 0) { ssc[0] = 0.f; ssc[1] = 0.f; ssc[2] = 0.f; }
            __syncthreads();

            if (tid < KCLS) {
                int cnt = scnt[n * 20 + tid];
                if (cnt > 20) {
                    atomicAdd(&ssc[0], g_rsum[n * KCLS + tid] / (float)cnt);
                    float nr = 0.f;
                    #pragma unroll 4
                    for (int c = 0; c < CDIM; ++c) {
                        float mv = ms[c * KCLS + tid];
                        nr = fmaf(mv, mv, nr);
                    }
                    atomicAdd(&ssc[2], sqrtf(nr));
                }
            }
            for (int idx = tid; idx < KCLS * KCLS; idx += 256) {
                int f = idx / KCLS, s = idx % KCLS;
                if (f != s && scnt[n * 20 + f] > 20 && scnt[n * 20 + s] > 20) {
                    float d2 = 0.f;
                    #pragma unroll 4
                    for (int c = 0; c < CDIM; ++c) {
                        float d = ms[c * KCLS + f] - ms[c * KCLS + s];
                        d2 = fmaf(d, d, d2);
                    }
                    float t = fmaxf(3.0f - sqrtf(d2), 0.f);   // 2*DELTA = 3.0
                    atomicAdd(&ssc[1], t * t);
                }
            }
            __syncthreads();

            if (tid == 0) {
                int nvi = 0;
                for (int k = 0; k < KCLS; ++k) nvi += (scnt[n * 20 + k] > 20);
                float nv = fmaxf((float)nvi, 1.f);
                float connect = fmaxf(nv * (nv - 1.f), 1.f);
                total += ssc[0] / nv + ssc[1] / connect + 0.001f * ssc[2] / nv;
            }
            __syncthreads();
        }
        if (tid == 0) out[0] = total * 0.25f;
    }
}

// ---------------------------------------------------------------------------
extern "C" void kernel_launch(void* const* d_in, const int* in_sizes, int n_in,
                              void* d_out, int out_size) {
    int pi = 0, ti = 1;
    if (n_in >= 2 && in_sizes[0] == NIMG * PPIX) { pi = 1; ti = 0; }  // robustness vs input order
    const float* predict = (const float*)d_in[pi];
    const void* target = (const void*)d_in[ti];
    float* out = (float*)d_out;

    k_all<<<NB, NT>>>(predict, target, (const int*)target, out);
}